// round 14
// baseline (speedup 1.0000x reference)
#include <cuda_runtime.h>
#include <cuda_bf16.h>
#include <math.h>
#include <stdint.h>

#define MAXN 50000
#define MAXE 800000
#define DIN 64
#define DOUT 128
#define KDIM 192
#define TE 128                 // edges per tile (persistent kernel)

// Scratch (device globals)
__device__ float g_ht[MAXN * DOUT];
__device__ float g_a[MAXE * 4];
__device__ float g_amax[MAXN * 4];
__device__ float g_denom[MAXN * 4];
// pre-split operands: row = [64 bf16 hi | 64 bf16 lo] = 256B
__device__ __nv_bfloat16 g_nsplit[MAXN * 128];
__device__ __nv_bfloat16 g_esplit[(size_t)MAXE * 128];
__device__ __nv_bfloat16 g_Wps[3 * 128 * 128];   // [chunk][n][hi64|lo64]

__device__ __forceinline__ void atomicMaxFloat(float* addr, float value) {
    if (value >= 0.0f) atomicMax((int*)addr, __float_as_int(value));
    else               atomicMin((unsigned int*)addr, __float_as_uint(value));
}

__device__ __forceinline__ void mma_bf16(float* d, const uint32_t* a, const uint32_t* b) {
    asm volatile(
        "mma.sync.aligned.m16n8k16.row.col.f32.bf16.bf16.f32 "
        "{%0,%1,%2,%3}, {%4,%5,%6,%7}, {%8,%9}, {%0,%1,%2,%3};"
        : "+f"(d[0]), "+f"(d[1]), "+f"(d[2]), "+f"(d[3])
        : "r"(a[0]), "r"(a[1]), "r"(a[2]), "r"(a[3]), "r"(b[0]), "r"(b[1]));
}
__device__ __forceinline__ void ldsm_x4(uint32_t* r, uint32_t addr) {
    asm volatile("ldmatrix.sync.aligned.m8n8.x4.shared.b16 {%0,%1,%2,%3}, [%4];"
        : "=r"(r[0]), "=r"(r[1]), "=r"(r[2]), "=r"(r[3]) : "r"(addr));
}
__device__ __forceinline__ uint32_t smem_u32(const void* p) {
    uint32_t a;
    asm("{ .reg .u64 t; cvta.to.shared.u64 t, %1; cvt.u32.u64 %0, t; }"
        : "=r"(a) : "l"(p));
    return a;
}
__device__ __forceinline__ void cp16(uint32_t smem_dst, const void* gsrc) {
    asm volatile("cp.async.cg.shared.global [%0], [%1], 16;"
        :: "r"(smem_dst), "l"(gsrc));
}
#define CP_COMMIT() asm volatile("cp.async.commit_group;" ::: "memory")
#define CP_WAIT(n)  asm volatile("cp.async.wait_group %0;" :: "n"(n) : "memory")

__device__ __forceinline__ void bsplit(float x, uint16_t& h, uint16_t& l) {
    __nv_bfloat16 bh = __float2bfloat16_rn(x);
    float r = x - __bfloat162float(bh);
    __nv_bfloat16 bl = __float2bfloat16_rn(r);
    h = __bfloat16_as_ushort(bh);
    l = __bfloat16_as_ushort(bl);
}

__device__ __forceinline__ unsigned long long pack2(float lo, float hi) {
    unsigned long long r;
    asm("mov.b64 %0, {%1, %2};" : "=l"(r) : "f"(lo), "f"(hi));
    return r;
}
__device__ __forceinline__ void unpack2(unsigned long long v, float& lo, float& hi) {
    asm("mov.b64 {%0, %1}, %2;" : "=f"(lo), "=f"(hi) : "l"(v));
}
__device__ __forceinline__ void fma2(unsigned long long& d, unsigned long long a,
                                     unsigned long long b) {
    asm("fma.rn.f32x2 %0, %1, %2, %0;" : "+l"(d) : "l"(a), "l"(b));
}

// ---------------------------------------------------------------------------
// node transform (launch 1): tiled f32x2 GEMM, 128 nodes x 128 cols per block
// ---------------------------------------------------------------------------
__global__ __launch_bounds__(512, 1)
void node_kernel(const float* __restrict__ nfeats,
                 const float* __restrict__ W_nodes,
                 const float* __restrict__ b_nodes,
                 int N) {
    __shared__ float Ws[DIN * DOUT];    // 32 KB
    __shared__ float Xt[DIN * 128];     // 32 KB, transposed [k][node]
    __shared__ float bsh[DOUT];

    int tid  = threadIdx.x;
    int lane = tid & 31;
    int warp = tid >> 5;
    int n0   = blockIdx.x * 128;

    for (int i = tid; i < DIN * DOUT / 4; i += 512)
        ((float4*)Ws)[i] = ((const float4*)W_nodes)[i];
    if (tid < DOUT) bsh[tid] = b_nodes[tid];

#pragma unroll
    for (int it = 0; it < 4; it++) {
        int i   = tid + it * 512;
        int ln  = i >> 4;
        int seg = i & 15;
        int n   = n0 + ln;
        float4 v = make_float4(0.f, 0.f, 0.f, 0.f);
        if (n < N) v = ((const float4*)(nfeats + (size_t)n * DIN))[seg];
        int k0 = seg * 4;
        Xt[(k0 + 0) * 128 + ln] = v.x;
        Xt[(k0 + 1) * 128 + ln] = v.y;
        Xt[(k0 + 2) * 128 + ln] = v.z;
        Xt[(k0 + 3) * 128 + ln] = v.w;
    }
    __syncthreads();

    int c0  = lane * 4;
    int ln0 = warp * 8;

    unsigned long long acc[4][4];
#pragma unroll
    for (int p = 0; p < 4; p++)
#pragma unroll
        for (int c = 0; c < 4; c++)
            acc[p][c] = pack2(bsh[c0 + c], bsh[c0 + c]);

#pragma unroll 2
    for (int k = 0; k < DIN; k++) {
        float4 w = *reinterpret_cast<const float4*>(Ws + k * DOUT + c0);
        unsigned long long wd[4];
        wd[0] = pack2(w.x, w.x);
        wd[1] = pack2(w.y, w.y);
        wd[2] = pack2(w.z, w.z);
        wd[3] = pack2(w.w, w.w);
        ulonglong2 sA = *reinterpret_cast<const ulonglong2*>(Xt + k * 128 + ln0);
        ulonglong2 sB = *reinterpret_cast<const ulonglong2*>(Xt + k * 128 + ln0 + 4);
        unsigned long long sp[4] = {sA.x, sA.y, sB.x, sB.y};
#pragma unroll
        for (int p = 0; p < 4; p++)
#pragma unroll
            for (int c = 0; c < 4; c++)
                fma2(acc[p][c], sp[p], wd[c]);
    }

#pragma unroll
    for (int p = 0; p < 4; p++) {
        float lo[4], hi[4];
#pragma unroll
        for (int c = 0; c < 4; c++) unpack2(acc[p][c], lo[c], hi[c]);
        int nA = n0 + ln0 + 2 * p;
        if (nA < N)
            *(float4*)(g_ht + (size_t)nA * DOUT + c0) =
                make_float4(lo[0], lo[1], lo[2], lo[3]);
        if (nA + 1 < N)
            *(float4*)(g_ht + (size_t)(nA + 1) * DOUT + c0) =
                make_float4(hi[0], hi[1], hi[2], hi[3]);
    }
}

// ---------------------------------------------------------------------------
// prep_w (launch 2): W split (chunk-major) + init amax/denom
// ---------------------------------------------------------------------------
__global__ void prep_w_kernel(const float* __restrict__ W_edges, int N) {
    int stride = gridDim.x * blockDim.x;
    int gid = blockIdx.x * blockDim.x + threadIdx.x;
    for (int i = gid; i < 3 * 128 * 64; i += stride) {
        int c  = i / (128 * 64);
        int n  = (i / 64) & 127;
        int kk = i & 63;
        float x = W_edges[(size_t)(64 * c + kk) * DOUT + n];
        uint16_t h, l;
        bsplit(x, h, l);
        __nv_bfloat16* row = g_Wps + ((size_t)c * 128 + n) * 128;
        row[kk]      = __ushort_as_bfloat16(h);
        row[64 + kk] = __ushort_as_bfloat16(l);
    }
    for (int i = gid; i < N * 4; i += stride) {
        g_amax[i]  = -INFINITY;
        g_denom[i] = 0.0f;
    }
}

// ---------------------------------------------------------------------------
// prep_feats (launch 3): nfeats + efeats bf16 hi/lo split
// ---------------------------------------------------------------------------
__global__ void prep_feats_kernel(const float* __restrict__ nfeats,
                                  const float* __restrict__ efeats,
                                  int N, int E) {
    int stride = gridDim.x * blockDim.x;
    int gid = blockIdx.x * blockDim.x + threadIdx.x;
    int ntasks = N * 16;
    for (int i = gid; i < ntasks; i += stride) {
        int n = i >> 4, s = i & 15;
        float4 v = ((const float4*)(nfeats + (size_t)n * DIN))[s];
        uint16_t h0, l0, h1, l1, h2, l2, h3, l3;
        bsplit(v.x, h0, l0); bsplit(v.y, h1, l1);
        bsplit(v.z, h2, l2); bsplit(v.w, h3, l3);
        uint2* row = (uint2*)(g_nsplit + (size_t)n * 128);
        row[s]      = make_uint2((uint32_t)h0 | ((uint32_t)h1 << 16),
                                 (uint32_t)h2 | ((uint32_t)h3 << 16));
        row[16 + s] = make_uint2((uint32_t)l0 | ((uint32_t)l1 << 16),
                                 (uint32_t)l2 | ((uint32_t)l3 << 16));
    }
    int etasks = E * 16;
    for (int i = gid; i < etasks; i += stride) {
        int e = i >> 4, s = i & 15;
        float4 v = ((const float4*)(efeats + (size_t)e * DIN))[s];
        uint16_t h0, l0, h1, l1, h2, l2, h3, l3;
        bsplit(v.x, h0, l0); bsplit(v.y, h1, l1);
        bsplit(v.z, h2, l2); bsplit(v.w, h3, l3);
        uint2* row = (uint2*)(g_esplit + (size_t)e * 128);
        row[s]      = make_uint2((uint32_t)h0 | ((uint32_t)h1 << 16),
                                 (uint32_t)h2 | ((uint32_t)h3 << 16));
        row[16 + s] = make_uint2((uint32_t)l0 | ((uint32_t)l1 << 16),
                                 (uint32_t)l2 | ((uint32_t)l3 << 16));
    }
}

// ---------------------------------------------------------------------------
// Edge kernel (launch 4): persistent, W resident, TRIPLE-BUFFERED A
// (one dedicated buffer per chunk; uniform CP_WAIT(2); next-tile chunk c
// issued the moment buffer c frees — every load gets >=2 phases of lead).
// 128 edges x 128 cols per tile, 512 threads (16 warps, 4m x 4n, 32x32 each).
// ---------------------------------------------------------------------------
#define ASTRIDE 144
#define CHUNKB  36864
#define SW_OFF(c) ((uint32_t)((c) * CHUNKB))            // W: 0..110592
#define SA_OFF(c) ((uint32_t)(110592 + (c) * CHUNKB))   // A buffer per chunk
#define LO_OFF  18432
#define SO_BS   221184
#define SO_WAS  221696
#define SO_TOTAL 221824

__global__ __launch_bounds__(512, 1)
void edge_kernel(const int* __restrict__ src,
                 const int* __restrict__ dst,
                 const float* __restrict__ b_edges,
                 const float* __restrict__ W_attn,
                 float* __restrict__ f_out,
                 int E, int ntiles) {
    extern __shared__ char smem[];
    float* bs  = (float*)(smem + SO_BS);
    float* was = (float*)(smem + SO_WAS);

    int tid  = threadIdx.x;
    int lane = tid & 31;
    int warp = tid >> 5;
    uint32_t sb = smem_u32(smem);
    int grid = gridDim.x;
    int t0 = blockIdx.x;
    if (t0 >= ntiles) return;     // before ANY cp.async

    if (tid < DOUT) bs[tid] = b_edges[tid];
    if (tid < 32)
        was[tid] = W_attn[tid * 4] + W_attn[tid * 4 + 1]
                 + W_attn[tid * 4 + 2] + W_attn[tid * 4 + 3];

    // ---- resident W: 3 chunks x 128 rows x 16 segs(16B); one group ----
#pragma unroll
    for (int it = 0; it < 12; it++) {
        int i   = tid + it * 512;          // 0..6143
        int c   = i >> 11;
        int n   = (i >> 4) & 127;
        int seg = i & 15;
        uint32_t dsto = SW_OFF(c) + ((seg < 8) ? 0 : LO_OFF) + n * ASTRIDE
                      + (seg & 7) * 16;
        const char* srcp = (const char*)g_Wps + ((size_t)c * 128 + n) * 256 + seg * 16;
        cp16(sb + dsto, srcp);
    }
    CP_COMMIT();   // W group; drains together with the first tile's first wait

    // ---- A-chunk issue: tile t, chunk c -> dedicated buffer c (one group) --
    auto issue = [&](int t, int c) {
        int e0 = t * TE;
#pragma unroll
        for (int it = 0; it < 4; it++) {
            int i   = tid + it * 512;      // 0..2047
            int le  = i >> 4;
            int seg = i & 15;
            int e   = e0 + le;
            int ee  = (e < E) ? e : (E - 1);
            const char* row;
            if (c == 0)      row = (const char*)(g_nsplit + (size_t)src[ee] * 128);
            else if (c == 1) row = (const char*)(g_esplit + (size_t)ee * 128);
            else             row = (const char*)(g_nsplit + (size_t)dst[ee] * 128);
            uint32_t dsto = SA_OFF(c) + ((seg < 8) ? 0 : LO_OFF) + le * ASTRIDE
                          + (seg & 7) * 16;
            cp16(sb + dsto, row + seg * 16);
        }
        CP_COMMIT();
    };

    // warp tile coords: 4m x 4n, 32x32 each; head = wn
    int wm = warp & 3;
    int wn = warp >> 2;
    int mrow0 = wm * 32;
    int nrow0 = wn * 32;
    uint32_t a_l_off = (uint32_t)((lane & 15) * ASTRIDE + (lane >> 4) * 16);
    uint32_t b_l_off = (uint32_t)(((lane & 7) + ((lane >> 4) << 3)) * ASTRIDE
                                + (((lane >> 3) & 1) << 4));
    int g   = lane >> 2;
    int tig = lane & 3;

    float acc[2][4][4];

    // compute one 64-K chunk: A from buffer c, W from resident chunk c
    auto compute = [&](int c) {
#pragma unroll
        for (int kk = 0; kk < 4; kk++) {
            uint32_t kb = kk * 32;
            uint32_t ah[2][4], al_[2][4], bh[2][4], bl_[2][4];
#pragma unroll
            for (int mt = 0; mt < 2; mt++) {
                uint32_t base = sb + SA_OFF(c)
                              + (mrow0 + mt * 16) * ASTRIDE + kb + a_l_off;
                ldsm_x4(ah[mt],  base);
                ldsm_x4(al_[mt], base + LO_OFF);
            }
#pragma unroll
            for (int p = 0; p < 2; p++) {
                uint32_t base = sb + SW_OFF(c)
                              + (nrow0 + p * 16) * ASTRIDE + kb + b_l_off;
                ldsm_x4(bh[p],  base);
                ldsm_x4(bl_[p], base + LO_OFF);
            }
#pragma unroll
            for (int mt = 0; mt < 2; mt++)
#pragma unroll
                for (int nt = 0; nt < 4; nt++) {
                    const uint32_t* bhf = &bh[nt >> 1][(nt & 1) * 2];
                    const uint32_t* blf = &bl_[nt >> 1][(nt & 1) * 2];
                    mma_bf16(acc[mt][nt], ah[mt], bhf);
                    mma_bf16(acc[mt][nt], ah[mt], blf);
                    mma_bf16(acc[mt][nt], al_[mt], bhf);
                }
        }
    };

    // prologue: first tile's three chunks, each its own group
    issue(t0, 0);
    issue(t0, 1);
    issue(t0, 2);

    for (int t = t0; t < ntiles; t += grid) {
#pragma unroll
        for (int mt = 0; mt < 2; mt++)
#pragma unroll
            for (int nt = 0; nt < 4; nt++)
#pragma unroll
                for (int q = 0; q < 4; q++) acc[mt][nt][q] = 0.0f;

        int tn = t + grid;
        bool pf = tn < ntiles;

        // chunk 0: pending(oldest first) = [c0, c1, c2]  (+W on first tile)
        CP_WAIT(2);
        __syncthreads();
        compute(0);
        __syncthreads();           // buffer 0 free
        if (pf) issue(tn, 0);      // pending: [c1, c2, n0]

        // chunk 1
        if (pf) { CP_WAIT(2); } else { CP_WAIT(1); }
        __syncthreads();
        compute(1);
        __syncthreads();           // buffer 1 free
        if (pf) issue(tn, 1);      // pending: [c2, n0, n1]

        // chunk 2
        if (pf) { CP_WAIT(2); } else { CP_WAIT(0); }
        __syncthreads();
        compute(2);
        __syncthreads();           // buffer 2 free
        if (pf) issue(tn, 2);      // pending: [n0, n1, n2]

        // ---- register epilogue (overlaps next tile's loads): head h = wn --
        int e0 = t * TE;
        int h  = wn;
#pragma unroll
        for (int mt = 0; mt < 2; mt++) {
#pragma unroll
            for (int rb = 0; rb < 2; rb++) {
                int e = e0 + mrow0 + mt * 16 + rb * 8 + g;
                float part = 0.0f;
#pragma unroll
                for (int nt = 0; nt < 4; nt++) {
                    int col  = nrow0 + nt * 8 + tig * 2;   // global column (bias)
                    int coli = nt * 8 + tig * 2;           // within-head (attn w)
                    float v0 = acc[mt][nt][rb * 2 + 0] + bs[col];
                    float v1 = acc[mt][nt][rb * 2 + 1] + bs[col + 1];
                    v0 = (v0 >= 0.f) ? v0 : 0.01f * v0;
                    v1 = (v1 >= 0.f) ? v1 : 0.01f * v1;
                    part += v0 * was[coli] + v1 * was[coli + 1];
                    if (e < E)
                        *(float2*)(f_out + (size_t)e * DOUT + col) =
                            make_float2(v0, v1);
                }
                part += __shfl_xor_sync(0xffffffffu, part, 1);
                part += __shfl_xor_sync(0xffffffffu, part, 2);
                if (tig == 0 && e < E) {
                    g_a[(size_t)e * 4 + h] = part;
                    atomicMaxFloat(&g_amax[(size_t)dst[e] * 4 + h], part);
                }
            }
        }
    }
}

// ---------------------------------------------------------------------------
// softmax (launch 5): also zero-inits h_out before scatter
// ---------------------------------------------------------------------------
__global__ void softmax2_kernel(const int* __restrict__ dst, float* h_out,
                                int E, int N) {
    int stride = gridDim.x * blockDim.x;
    int total_h = N * DOUT;
    for (int i = blockIdx.x * blockDim.x + threadIdx.x; i < total_h; i += stride)
        h_out[i] = 0.0f;
    int total = E * 4;
    for (int i = blockIdx.x * blockDim.x + threadIdx.x; i < total; i += stride) {
        int e = i >> 2;
        int h = i & 3;
        int d = dst[e];
        float v = expf(g_a[i] - g_amax[d * 4 + h]);
        g_a[i] = v;
        atomicAdd(&g_denom[d * 4 + h], v);
    }
}

__global__ void scatter_kernel(const int* __restrict__ src,
                               const int* __restrict__ dst,
                               float* __restrict__ h_out,
                               int E) {
    int gwarp = (blockIdx.x * blockDim.x + threadIdx.x) >> 5;
    int lane  = threadIdx.x & 31;
    if (gwarp >= E) return;
    int s = src[gwarp];
    int d = dst[gwarp];
    int h = lane >> 3;
    float alpha = g_a[(size_t)gwarp * 4 + h] / g_denom[(size_t)d * 4 + h];
    float4 ht = *reinterpret_cast<const float4*>(g_ht + (size_t)s * DOUT + lane * 4);
    float4 v = make_float4(alpha * ht.x, alpha * ht.y, alpha * ht.z, alpha * ht.w);
    atomicAdd(reinterpret_cast<float4*>(h_out + (size_t)d * DOUT + lane * 4), v);
}

// ---------------------------------------------------------------------------
extern "C" void kernel_launch(void* const* d_in, const int* in_sizes, int n_in,
                              void* d_out, int out_size) {
    const float* nfeats  = (const float*)d_in[0];
    const float* efeats  = (const float*)d_in[1];
    const int*   src     = (const int*)d_in[2];
    const int*   dst     = (const int*)d_in[3];
    const float* W_nodes = (const float*)d_in[4];
    const float* b_nodes = (const float*)d_in[5];
    const float* W_edges = (const float*)d_in[6];
    const float* b_edges = (const float*)d_in[7];
    const float* W_attn  = (const float*)d_in[8];

    int N = in_sizes[0] / DIN;
    int E = in_sizes[2];
    int ntiles = (E + TE - 1) / TE;

    float* h_out = (float*)d_out;
    float* f_out = (float*)d_out + (size_t)N * DOUT;

    cudaFuncSetAttribute(edge_kernel, cudaFuncAttributeMaxDynamicSharedMemorySize,
                         SO_TOTAL);

    node_kernel<<<(N + 127) / 128, 512>>>(nfeats, W_nodes, b_nodes, N);
    prep_w_kernel<<<256, 256>>>(W_edges, N);
    prep_feats_kernel<<<1024, 256>>>(nfeats, efeats, N, E);
    edge_kernel<<<148, 512, SO_TOTAL>>>(src, dst, b_edges, W_attn, f_out, E, ntiles);
    softmax2_kernel<<<1024, 256>>>(dst, h_out, E, N);
    scatter_kernel<<<(E * 32 + 255) / 256, 256>>>(src, dst, h_out, E);
}

// round 15
// speedup vs baseline: 1.1087x; 1.1087x over previous
#include <cuda_runtime.h>
#include <cuda_bf16.h>
#include <math.h>
#include <stdint.h>

#define MAXN 50000
#define MAXE 800000
#define DIN 64
#define DOUT 128
#define KDIM 192
#define TE 128                 // edges per tile (persistent kernel)

// Scratch (device globals)
__device__ float g_ht[MAXN * DOUT];
__device__ float g_a[MAXE * 4];
__device__ float g_amax[MAXN * 4];
__device__ float g_denom[MAXN * 4];
// pre-split operands: row = [64 bf16 hi | 64 bf16 lo] = 256B
__device__ __nv_bfloat16 g_nsplit[MAXN * 128];
__device__ __nv_bfloat16 g_esplit[(size_t)MAXE * 128];
__device__ __nv_bfloat16 g_Wps[3 * 128 * 128];   // [chunk][n][hi64|lo64]

__device__ __forceinline__ void atomicMaxFloat(float* addr, float value) {
    if (value >= 0.0f) atomicMax((int*)addr, __float_as_int(value));
    else               atomicMin((unsigned int*)addr, __float_as_uint(value));
}

__device__ __forceinline__ void mma_bf16(float* d, const uint32_t* a, const uint32_t* b) {
    asm volatile(
        "mma.sync.aligned.m16n8k16.row.col.f32.bf16.bf16.f32 "
        "{%0,%1,%2,%3}, {%4,%5,%6,%7}, {%8,%9}, {%0,%1,%2,%3};"
        : "+f"(d[0]), "+f"(d[1]), "+f"(d[2]), "+f"(d[3])
        : "r"(a[0]), "r"(a[1]), "r"(a[2]), "r"(a[3]), "r"(b[0]), "r"(b[1]));
}
__device__ __forceinline__ void ldsm_x4(uint32_t* r, uint32_t addr) {
    asm volatile("ldmatrix.sync.aligned.m8n8.x4.shared.b16 {%0,%1,%2,%3}, [%4];"
        : "=r"(r[0]), "=r"(r[1]), "=r"(r[2]), "=r"(r[3]) : "r"(addr));
}
__device__ __forceinline__ uint32_t smem_u32(const void* p) {
    uint32_t a;
    asm("{ .reg .u64 t; cvta.to.shared.u64 t, %1; cvt.u32.u64 %0, t; }"
        : "=r"(a) : "l"(p));
    return a;
}
__device__ __forceinline__ void cp16(uint32_t smem_dst, const void* gsrc) {
    asm volatile("cp.async.cg.shared.global [%0], [%1], 16;"
        :: "r"(smem_dst), "l"(gsrc));
}
#define CP_COMMIT() asm volatile("cp.async.commit_group;" ::: "memory")
#define CP_WAIT(n)  asm volatile("cp.async.wait_group %0;" :: "n"(n) : "memory")

__device__ __forceinline__ void bsplit(float x, uint16_t& h, uint16_t& l) {
    __nv_bfloat16 bh = __float2bfloat16_rn(x);
    float r = x - __bfloat162float(bh);
    __nv_bfloat16 bl = __float2bfloat16_rn(r);
    h = __bfloat16_as_ushort(bh);
    l = __bfloat16_as_ushort(bl);
}

__device__ __forceinline__ unsigned long long pack2(float lo, float hi) {
    unsigned long long r;
    asm("mov.b64 %0, {%1, %2};" : "=l"(r) : "f"(lo), "f"(hi));
    return r;
}
__device__ __forceinline__ void unpack2(unsigned long long v, float& lo, float& hi) {
    asm("mov.b64 {%0, %1}, %2;" : "=f"(lo), "=f"(hi) : "l"(v));
}
__device__ __forceinline__ void fma2(unsigned long long& d, unsigned long long a,
                                     unsigned long long b) {
    asm("fma.rn.f32x2 %0, %1, %2, %0;" : "+l"(d) : "l"(a), "l"(b));
}

// ---------------------------------------------------------------------------
// node transform: tiled f32x2 GEMM, 128 nodes x 128 cols per block
// ---------------------------------------------------------------------------
__global__ __launch_bounds__(512, 1)
void node_kernel(const float* __restrict__ nfeats,
                 const float* __restrict__ W_nodes,
                 const float* __restrict__ b_nodes,
                 int N) {
    __shared__ float Ws[DIN * DOUT];    // 32 KB
    __shared__ float Xt[DIN * 128];     // 32 KB, transposed [k][node]
    __shared__ float bsh[DOUT];

    int tid  = threadIdx.x;
    int lane = tid & 31;
    int warp = tid >> 5;
    int n0   = blockIdx.x * 128;

    for (int i = tid; i < DIN * DOUT / 4; i += 512)
        ((float4*)Ws)[i] = ((const float4*)W_nodes)[i];
    if (tid < DOUT) bsh[tid] = b_nodes[tid];

#pragma unroll
    for (int it = 0; it < 4; it++) {
        int i   = tid + it * 512;
        int ln  = i >> 4;
        int seg = i & 15;
        int n   = n0 + ln;
        float4 v = make_float4(0.f, 0.f, 0.f, 0.f);
        if (n < N) v = ((const float4*)(nfeats + (size_t)n * DIN))[seg];
        int k0 = seg * 4;
        Xt[(k0 + 0) * 128 + ln] = v.x;
        Xt[(k0 + 1) * 128 + ln] = v.y;
        Xt[(k0 + 2) * 128 + ln] = v.z;
        Xt[(k0 + 3) * 128 + ln] = v.w;
    }
    __syncthreads();

    int c0  = lane * 4;
    int ln0 = warp * 8;

    unsigned long long acc[4][4];
#pragma unroll
    for (int p = 0; p < 4; p++)
#pragma unroll
        for (int c = 0; c < 4; c++)
            acc[p][c] = pack2(bsh[c0 + c], bsh[c0 + c]);

#pragma unroll 2
    for (int k = 0; k < DIN; k++) {
        float4 w = *reinterpret_cast<const float4*>(Ws + k * DOUT + c0);
        unsigned long long wd[4];
        wd[0] = pack2(w.x, w.x);
        wd[1] = pack2(w.y, w.y);
        wd[2] = pack2(w.z, w.z);
        wd[3] = pack2(w.w, w.w);
        ulonglong2 sA = *reinterpret_cast<const ulonglong2*>(Xt + k * 128 + ln0);
        ulonglong2 sB = *reinterpret_cast<const ulonglong2*>(Xt + k * 128 + ln0 + 4);
        unsigned long long sp[4] = {sA.x, sA.y, sB.x, sB.y};
#pragma unroll
        for (int p = 0; p < 4; p++)
#pragma unroll
            for (int c = 0; c < 4; c++)
                fma2(acc[p][c], sp[p], wd[c]);
    }

#pragma unroll
    for (int p = 0; p < 4; p++) {
        float lo[4], hi[4];
#pragma unroll
        for (int c = 0; c < 4; c++) unpack2(acc[p][c], lo[c], hi[c]);
        int nA = n0 + ln0 + 2 * p;
        if (nA < N)
            *(float4*)(g_ht + (size_t)nA * DOUT + c0) =
                make_float4(lo[0], lo[1], lo[2], lo[3]);
        if (nA + 1 < N)
            *(float4*)(g_ht + (size_t)(nA + 1) * DOUT + c0) =
                make_float4(hi[0], hi[1], hi[2], hi[3]);
    }
}

// ---------------------------------------------------------------------------
// prep_w: W split (chunk-major) + init amax/denom + zero h_out
// ---------------------------------------------------------------------------
__global__ void prep_w_kernel(const float* __restrict__ W_edges,
                              float* __restrict__ h_out, int N) {
    int stride = gridDim.x * blockDim.x;
    int gid = blockIdx.x * blockDim.x + threadIdx.x;
    for (int i = gid; i < 3 * 128 * 64; i += stride) {
        int c  = i / (128 * 64);
        int n  = (i / 64) & 127;
        int kk = i & 63;
        float x = W_edges[(size_t)(64 * c + kk) * DOUT + n];
        uint16_t h, l;
        bsplit(x, h, l);
        __nv_bfloat16* row = g_Wps + ((size_t)c * 128 + n) * 128;
        row[kk]      = __ushort_as_bfloat16(h);
        row[64 + kk] = __ushort_as_bfloat16(l);
    }
    for (int i = gid; i < N * 4; i += stride) {
        g_amax[i]  = -INFINITY;
        g_denom[i] = 0.0f;
    }
    int total_h = N * DOUT;
    for (int i = gid; i < total_h; i += stride)
        h_out[i] = 0.0f;
}

// ---------------------------------------------------------------------------
// prep_feats: nfeats + efeats bf16 hi/lo split
// ---------------------------------------------------------------------------
__global__ void prep_feats_kernel(const float* __restrict__ nfeats,
                                  const float* __restrict__ efeats,
                                  int N, int E) {
    int stride = gridDim.x * blockDim.x;
    int gid = blockIdx.x * blockDim.x + threadIdx.x;
    int ntasks = N * 16;
    for (int i = gid; i < ntasks; i += stride) {
        int n = i >> 4, s = i & 15;
        float4 v = ((const float4*)(nfeats + (size_t)n * DIN))[s];
        uint16_t h0, l0, h1, l1, h2, l2, h3, l3;
        bsplit(v.x, h0, l0); bsplit(v.y, h1, l1);
        bsplit(v.z, h2, l2); bsplit(v.w, h3, l3);
        uint2* row = (uint2*)(g_nsplit + (size_t)n * 128);
        row[s]      = make_uint2((uint32_t)h0 | ((uint32_t)h1 << 16),
                                 (uint32_t)h2 | ((uint32_t)h3 << 16));
        row[16 + s] = make_uint2((uint32_t)l0 | ((uint32_t)l1 << 16),
                                 (uint32_t)l2 | ((uint32_t)l3 << 16));
    }
    int etasks = E * 16;
    for (int i = gid; i < etasks; i += stride) {
        int e = i >> 4, s = i & 15;
        float4 v = ((const float4*)(efeats + (size_t)e * DIN))[s];
        uint16_t h0, l0, h1, l1, h2, l2, h3, l3;
        bsplit(v.x, h0, l0); bsplit(v.y, h1, l1);
        bsplit(v.z, h2, l2); bsplit(v.w, h3, l3);
        uint2* row = (uint2*)(g_esplit + (size_t)e * 128);
        row[s]      = make_uint2((uint32_t)h0 | ((uint32_t)h1 << 16),
                                 (uint32_t)h2 | ((uint32_t)h3 << 16));
        row[16 + s] = make_uint2((uint32_t)l0 | ((uint32_t)l1 << 16),
                                 (uint32_t)l2 | ((uint32_t)l3 << 16));
    }
}

// ---------------------------------------------------------------------------
// Edge kernel: R13-proven version VERBATIM — persistent, W resident,
// per-tile self-contained cp.async pipeline (369.9 us / tensor 52.5%).
// ---------------------------------------------------------------------------
#define ASTRIDE 144
#define CHUNKB  36864
#define SW_OFF(c) ((uint32_t)((c) * CHUNKB))
#define SA_OFF(s) ((uint32_t)(110592 + (s) * CHUNKB))
#define LO_OFF  18432
#define SO_BS   184320
#define SO_WAS  184832
#define SO_TOTAL 184960

__global__ __launch_bounds__(512, 1)
void edge_kernel(const int* __restrict__ src,
                 const int* __restrict__ dst,
                 const float* __restrict__ b_edges,
                 const float* __restrict__ W_attn,
                 float* __restrict__ f_out,
                 int E, int ntiles) {
    extern __shared__ char smem[];
    float* bs  = (float*)(smem + SO_BS);
    float* was = (float*)(smem + SO_WAS);

    int tid  = threadIdx.x;
    int lane = tid & 31;
    int warp = tid >> 5;
    uint32_t sb = smem_u32(smem);
    int grid = gridDim.x;
    int t0 = blockIdx.x;
    if (t0 >= ntiles) return;     // before ANY cp.async

    if (tid < DOUT) bs[tid] = b_edges[tid];
    if (tid < 32)
        was[tid] = W_attn[tid * 4] + W_attn[tid * 4 + 1]
                 + W_attn[tid * 4 + 2] + W_attn[tid * 4 + 3];

    // ---- resident W: 3 chunks x 128 rows x 16 segs(16B); one group ----
#pragma unroll
    for (int it = 0; it < 12; it++) {
        int i   = tid + it * 512;          // 0..6143
        int c   = i >> 11;
        int n   = (i >> 4) & 127;
        int seg = i & 15;
        uint32_t dsto = SW_OFF(c) + ((seg < 8) ? 0 : LO_OFF) + n * ASTRIDE
                      + (seg & 7) * 16;
        const char* srcp = (const char*)g_Wps + ((size_t)c * 128 + n) * 256 + seg * 16;
        cp16(sb + dsto, srcp);
    }
    CP_COMMIT();   // W group; consumed by the first tile's wait(1)

    // ---- A-chunk issue: tile t, chunk c, stage s ----
    auto issue = [&](int t, int c, int s) {
        int e0 = t * TE;
#pragma unroll
        for (int it = 0; it < 4; it++) {
            int i   = tid + it * 512;      // 0..2047
            int le  = i >> 4;
            int seg = i & 15;
            int e   = e0 + le;
            int ee  = (e < E) ? e : (E - 1);
            const char* row;
            if (c == 0)      row = (const char*)(g_nsplit + (size_t)src[ee] * 128);
            else if (c == 1) row = (const char*)(g_esplit + (size_t)ee * 128);
            else             row = (const char*)(g_nsplit + (size_t)dst[ee] * 128);
            uint32_t dsto = SA_OFF(s) + ((seg < 8) ? 0 : LO_OFF) + le * ASTRIDE
                          + (seg & 7) * 16;
            cp16(sb + dsto, row + seg * 16);
        }
        CP_COMMIT();
    };

    // warp tile coords: 4m x 4n, 32x32 each; head = wn
    int wm = warp & 3;
    int wn = warp >> 2;
    int mrow0 = wm * 32;
    int nrow0 = wn * 32;
    uint32_t a_l_off = (uint32_t)((lane & 15) * ASTRIDE + (lane >> 4) * 16);
    uint32_t b_l_off = (uint32_t)(((lane & 7) + ((lane >> 4) << 3)) * ASTRIDE
                                + (((lane >> 3) & 1) << 4));
    int g   = lane >> 2;
    int tig = lane & 3;

    float acc[2][4][4];

    // compute one 64-K chunk: A from stage s, W from resident chunk c
    auto compute = [&](int c, int s) {
#pragma unroll
        for (int kk = 0; kk < 4; kk++) {
            uint32_t kb = kk * 32;
            uint32_t ah[2][4], al_[2][4], bh[2][4], bl_[2][4];
#pragma unroll
            for (int mt = 0; mt < 2; mt++) {
                uint32_t base = sb + SA_OFF(s)
                              + (mrow0 + mt * 16) * ASTRIDE + kb + a_l_off;
                ldsm_x4(ah[mt],  base);
                ldsm_x4(al_[mt], base + LO_OFF);
            }
#pragma unroll
            for (int p = 0; p < 2; p++) {
                uint32_t base = sb + SW_OFF(c)
                              + (nrow0 + p * 16) * ASTRIDE + kb + b_l_off;
                ldsm_x4(bh[p],  base);
                ldsm_x4(bl_[p], base + LO_OFF);
            }
#pragma unroll
            for (int mt = 0; mt < 2; mt++)
#pragma unroll
                for (int nt = 0; nt < 4; nt++) {
                    const uint32_t* bhf = &bh[nt >> 1][(nt & 1) * 2];
                    const uint32_t* blf = &bl_[nt >> 1][(nt & 1) * 2];
                    mma_bf16(acc[mt][nt], ah[mt], bhf);
                    mma_bf16(acc[mt][nt], ah[mt], blf);
                    mma_bf16(acc[mt][nt], al_[mt], bhf);
                }
        }
    };

    for (int t = t0; t < ntiles; t += grid) {
#pragma unroll
        for (int mt = 0; mt < 2; mt++)
#pragma unroll
            for (int nt = 0; nt < 4; nt++)
#pragma unroll
                for (int q = 0; q < 4; q++) acc[mt][nt][q] = 0.0f;

        issue(t, 0, 0);            // group: chunk0 -> stage0
        issue(t, 1, 1);            // group: chunk1 -> stage1

        CP_WAIT(1);                // chunk0 (and W on first tile) complete
        __syncthreads();
        compute(0, 0);
        __syncthreads();           // stage0 free
        issue(t, 2, 0);            // group: chunk2 -> stage0

        CP_WAIT(1);                // chunk1 complete
        __syncthreads();
        compute(1, 1);

        CP_WAIT(0);                // chunk2 complete (pipeline fully drained)
        __syncthreads();
        compute(2, 0);
        __syncthreads();           // all reads done before next tile's issues

        // ---- register epilogue: head h = wn ----
        int e0 = t * TE;
        int h  = wn;
#pragma unroll
        for (int mt = 0; mt < 2; mt++) {
#pragma unroll
            for (int rb = 0; rb < 2; rb++) {
                int e = e0 + mrow0 + mt * 16 + rb * 8 + g;
                float part = 0.0f;
#pragma unroll
                for (int nt = 0; nt < 4; nt++) {
                    int col  = nrow0 + nt * 8 + tig * 2;   // global column (bias)
                    int coli = nt * 8 + tig * 2;           // within-head (attn w)
                    float v0 = acc[mt][nt][rb * 2 + 0] + bs[col];
                    float v1 = acc[mt][nt][rb * 2 + 1] + bs[col + 1];
                    v0 = (v0 >= 0.f) ? v0 : 0.01f * v0;
                    v1 = (v1 >= 0.f) ? v1 : 0.01f * v1;
                    part += v0 * was[coli] + v1 * was[coli + 1];
                    if (e < E)
                        *(float2*)(f_out + (size_t)e * DOUT + col) =
                            make_float2(v0, v1);
                }
                part += __shfl_xor_sync(0xffffffffu, part, 1);
                part += __shfl_xor_sync(0xffffffffu, part, 2);
                if (tig == 0 && e < E) {
                    g_a[(size_t)e * 4 + h] = part;
                    atomicMaxFloat(&g_amax[(size_t)dst[e] * 4 + h], part);
                }
            }
        }
    }
}

// ---------------------------------------------------------------------------
// softmax: exp(a - amax[dst]) and segment-sum denom (h_out zeroed in prep_w)
// ---------------------------------------------------------------------------
__global__ void softmax_kernel(const int* __restrict__ dst, int E) {
    int stride = gridDim.x * blockDim.x;
    int total = E * 4;
    for (int i = blockIdx.x * blockDim.x + threadIdx.x; i < total; i += stride) {
        int e = i >> 2;
        int h = i & 3;
        int d = dst[e];
        float v = expf(g_a[i] - g_amax[d * 4 + h]);
        g_a[i] = v;
        atomicAdd(&g_denom[d * 4 + h], v);
    }
}

__global__ void scatter_kernel(const int* __restrict__ src,
                               const int* __restrict__ dst,
                               float* __restrict__ h_out,
                               int E) {
    int gwarp = (blockIdx.x * blockDim.x + threadIdx.x) >> 5;
    int lane  = threadIdx.x & 31;
    if (gwarp >= E) return;
    int s = src[gwarp];
    int d = dst[gwarp];
    int h = lane >> 3;
    float alpha = g_a[(size_t)gwarp * 4 + h] / g_denom[(size_t)d * 4 + h];
    float4 ht = *reinterpret_cast<const float4*>(g_ht + (size_t)s * DOUT + lane * 4);
    float4 v = make_float4(alpha * ht.x, alpha * ht.y, alpha * ht.z, alpha * ht.w);
    atomicAdd(reinterpret_cast<float4*>(h_out + (size_t)d * DOUT + lane * 4), v);
}

// ---------------------------------------------------------------------------
extern "C" void kernel_launch(void* const* d_in, const int* in_sizes, int n_in,
                              void* d_out, int out_size) {
    const float* nfeats  = (const float*)d_in[0];
    const float* efeats  = (const float*)d_in[1];
    const int*   src     = (const int*)d_in[2];
    const int*   dst     = (const int*)d_in[3];
    const float* W_nodes = (const float*)d_in[4];
    const float* b_nodes = (const float*)d_in[5];
    const float* W_edges = (const float*)d_in[6];
    const float* b_edges = (const float*)d_in[7];
    const float* W_attn  = (const float*)d_in[8];

    int N = in_sizes[0] / DIN;
    int E = in_sizes[2];
    int ntiles = (E + TE - 1) / TE;

    float* h_out = (float*)d_out;
    float* f_out = (float*)d_out + (size_t)N * DOUT;

    cudaFuncSetAttribute(edge_kernel, cudaFuncAttributeMaxDynamicSharedMemorySize,
                         SO_TOTAL);

    // one-time host resources (initialized on the correctness run, reused in
    // graph capture — no device allocation involved)
    static cudaStream_t s1 = nullptr, s2 = nullptr;
    static cudaEvent_t ev_fork = nullptr, ev_s1 = nullptr, ev_s2 = nullptr;
    if (s1 == nullptr) {
        cudaStreamCreateWithFlags(&s1, cudaStreamNonBlocking);
        cudaStreamCreateWithFlags(&s2, cudaStreamNonBlocking);
        cudaEventCreateWithFlags(&ev_fork, cudaEventDisableTiming);
        cudaEventCreateWithFlags(&ev_s1, cudaEventDisableTiming);
        cudaEventCreateWithFlags(&ev_s2, cudaEventDisableTiming);
    }

    // fork: node (stream 0) || prep_w (s1) || prep_feats (s2)
    cudaEventRecord(ev_fork, 0);
    cudaStreamWaitEvent(s1, ev_fork, 0);
    cudaStreamWaitEvent(s2, ev_fork, 0);

    node_kernel<<<(N + 127) / 128, 512>>>(nfeats, W_nodes, b_nodes, N);
    prep_w_kernel<<<256, 256, 0, s1>>>(W_edges, h_out, N);
    prep_feats_kernel<<<1024, 256, 0, s2>>>(nfeats, efeats, N, E);

    cudaEventRecord(ev_s1, s1);
    cudaEventRecord(ev_s2, s2);
    cudaStreamWaitEvent(0, ev_s1, 0);
    cudaStreamWaitEvent(0, ev_s2, 0);

    edge_kernel<<<148, 512, SO_TOTAL>>>(src, dst, b_edges, W_attn, f_out, E, ntiles);
    softmax_kernel<<<1024, 256>>>(dst, E);
    scatter_kernel<<<(E * 32 + 255) / 256, 256>>>(src, dst, h_out, E);
}

// round 16
// speedup vs baseline: 1.1867x; 1.0704x over previous
#include <cuda_runtime.h>
#include <cuda_bf16.h>
#include <math.h>
#include <stdint.h>

#define MAXN 50000
#define MAXE 800000
#define DIN 64
#define DOUT 128
#define KDIM 192
#define TE 128                 // edges per tile (persistent kernel)

// Scratch (device globals)
__device__ float g_ht[MAXN * DOUT];
__device__ float g_a[MAXE * 4];          // attention logits
__device__ float g_amax[MAXN * 4];
// CSR scratch
__device__ int   g_cnt[MAXN];
__device__ int   g_off[MAXN + 1];
__device__ int   g_cur[MAXN];
__device__ int   g_eid[MAXE];
__device__ int   g_esrc[MAXE];
// pre-split operands: row = [64 bf16 hi | 64 bf16 lo] = 256B
__device__ __nv_bfloat16 g_nsplit[MAXN * 128];
__device__ __nv_bfloat16 g_esplit[(size_t)MAXE * 128];
__device__ __nv_bfloat16 g_Wps[3 * 128 * 128];   // [chunk][n][hi64|lo64]

__device__ __forceinline__ void atomicMaxFloat(float* addr, float value) {
    if (value >= 0.0f) atomicMax((int*)addr, __float_as_int(value));
    else               atomicMin((unsigned int*)addr, __float_as_uint(value));
}

__device__ __forceinline__ void mma_bf16(float* d, const uint32_t* a, const uint32_t* b) {
    asm volatile(
        "mma.sync.aligned.m16n8k16.row.col.f32.bf16.bf16.f32 "
        "{%0,%1,%2,%3}, {%4,%5,%6,%7}, {%8,%9}, {%0,%1,%2,%3};"
        : "+f"(d[0]), "+f"(d[1]), "+f"(d[2]), "+f"(d[3])
        : "r"(a[0]), "r"(a[1]), "r"(a[2]), "r"(a[3]), "r"(b[0]), "r"(b[1]));
}
__device__ __forceinline__ void ldsm_x4(uint32_t* r, uint32_t addr) {
    asm volatile("ldmatrix.sync.aligned.m8n8.x4.shared.b16 {%0,%1,%2,%3}, [%4];"
        : "=r"(r[0]), "=r"(r[1]), "=r"(r[2]), "=r"(r[3]) : "r"(addr));
}
__device__ __forceinline__ uint32_t smem_u32(const void* p) {
    uint32_t a;
    asm("{ .reg .u64 t; cvta.to.shared.u64 t, %1; cvt.u32.u64 %0, t; }"
        : "=r"(a) : "l"(p));
    return a;
}
__device__ __forceinline__ void cp16(uint32_t smem_dst, const void* gsrc) {
    asm volatile("cp.async.cg.shared.global [%0], [%1], 16;"
        :: "r"(smem_dst), "l"(gsrc));
}
#define CP_COMMIT() asm volatile("cp.async.commit_group;" ::: "memory")
#define CP_WAIT(n)  asm volatile("cp.async.wait_group %0;" :: "n"(n) : "memory")

__device__ __forceinline__ void bsplit(float x, uint16_t& h, uint16_t& l) {
    __nv_bfloat16 bh = __float2bfloat16_rn(x);
    float r = x - __bfloat162float(bh);
    __nv_bfloat16 bl = __float2bfloat16_rn(r);
    h = __bfloat16_as_ushort(bh);
    l = __bfloat16_as_ushort(bl);
}

__device__ __forceinline__ unsigned long long pack2(float lo, float hi) {
    unsigned long long r;
    asm("mov.b64 %0, {%1, %2};" : "=l"(r) : "f"(lo), "f"(hi));
    return r;
}
__device__ __forceinline__ void unpack2(unsigned long long v, float& lo, float& hi) {
    asm("mov.b64 {%0, %1}, %2;" : "=f"(lo), "=f"(hi) : "l"(v));
}
__device__ __forceinline__ void fma2(unsigned long long& d, unsigned long long a,
                                     unsigned long long b) {
    asm("fma.rn.f32x2 %0, %1, %2, %0;" : "+l"(d) : "l"(a), "l"(b));
}

// ---------------------------------------------------------------------------
// node transform: tiled f32x2 GEMM, 128 nodes x 128 cols per block
// ---------------------------------------------------------------------------
__global__ __launch_bounds__(512, 1)
void node_kernel(const float* __restrict__ nfeats,
                 const float* __restrict__ W_nodes,
                 const float* __restrict__ b_nodes,
                 int N) {
    __shared__ float Ws[DIN * DOUT];    // 32 KB
    __shared__ float Xt[DIN * 128];     // 32 KB, transposed [k][node]
    __shared__ float bsh[DOUT];

    int tid  = threadIdx.x;
    int lane = tid & 31;
    int warp = tid >> 5;
    int n0   = blockIdx.x * 128;

    for (int i = tid; i < DIN * DOUT / 4; i += 512)
        ((float4*)Ws)[i] = ((const float4*)W_nodes)[i];
    if (tid < DOUT) bsh[tid] = b_nodes[tid];

#pragma unroll
    for (int it = 0; it < 4; it++) {
        int i   = tid + it * 512;
        int ln  = i >> 4;
        int seg = i & 15;
        int n   = n0 + ln;
        float4 v = make_float4(0.f, 0.f, 0.f, 0.f);
        if (n < N) v = ((const float4*)(nfeats + (size_t)n * DIN))[seg];
        int k0 = seg * 4;
        Xt[(k0 + 0) * 128 + ln] = v.x;
        Xt[(k0 + 1) * 128 + ln] = v.y;
        Xt[(k0 + 2) * 128 + ln] = v.z;
        Xt[(k0 + 3) * 128 + ln] = v.w;
    }
    __syncthreads();

    int c0  = lane * 4;
    int ln0 = warp * 8;

    unsigned long long acc[4][4];
#pragma unroll
    for (int p = 0; p < 4; p++)
#pragma unroll
        for (int c = 0; c < 4; c++)
            acc[p][c] = pack2(bsh[c0 + c], bsh[c0 + c]);

#pragma unroll 2
    for (int k = 0; k < DIN; k++) {
        float4 w = *reinterpret_cast<const float4*>(Ws + k * DOUT + c0);
        unsigned long long wd[4];
        wd[0] = pack2(w.x, w.x);
        wd[1] = pack2(w.y, w.y);
        wd[2] = pack2(w.z, w.z);
        wd[3] = pack2(w.w, w.w);
        ulonglong2 sA = *reinterpret_cast<const ulonglong2*>(Xt + k * 128 + ln0);
        ulonglong2 sB = *reinterpret_cast<const ulonglong2*>(Xt + k * 128 + ln0 + 4);
        unsigned long long sp[4] = {sA.x, sA.y, sB.x, sB.y};
#pragma unroll
        for (int p = 0; p < 4; p++)
#pragma unroll
            for (int c = 0; c < 4; c++)
                fma2(acc[p][c], sp[p], wd[c]);
    }

#pragma unroll
    for (int p = 0; p < 4; p++) {
        float lo[4], hi[4];
#pragma unroll
        for (int c = 0; c < 4; c++) unpack2(acc[p][c], lo[c], hi[c]);
        int nA = n0 + ln0 + 2 * p;
        if (nA < N)
            *(float4*)(g_ht + (size_t)nA * DOUT + c0) =
                make_float4(lo[0], lo[1], lo[2], lo[3]);
        if (nA + 1 < N)
            *(float4*)(g_ht + (size_t)(nA + 1) * DOUT + c0) =
                make_float4(hi[0], hi[1], hi[2], hi[3]);
    }
}

// ---------------------------------------------------------------------------
// prep_w: W split (chunk-major) + init amax + zero CSR counters
// ---------------------------------------------------------------------------
__global__ void prep_w_kernel(const float* __restrict__ W_edges, int N) {
    int stride = gridDim.x * blockDim.x;
    int gid = blockIdx.x * blockDim.x + threadIdx.x;
    for (int i = gid; i < 3 * 128 * 64; i += stride) {
        int c  = i / (128 * 64);
        int n  = (i / 64) & 127;
        int kk = i & 63;
        float x = W_edges[(size_t)(64 * c + kk) * DOUT + n];
        uint16_t h, l;
        bsplit(x, h, l);
        __nv_bfloat16* row = g_Wps + ((size_t)c * 128 + n) * 128;
        row[kk]      = __ushort_as_bfloat16(h);
        row[64 + kk] = __ushort_as_bfloat16(l);
    }
    for (int i = gid; i < N * 4; i += stride)
        g_amax[i] = -INFINITY;
    for (int i = gid; i < N; i += stride)
        g_cnt[i] = 0;
}

// ---------------------------------------------------------------------------
// prep_feats: nfeats + efeats bf16 hi/lo split
// ---------------------------------------------------------------------------
__global__ void prep_feats_kernel(const float* __restrict__ nfeats,
                                  const float* __restrict__ efeats,
                                  int N, int E) {
    int stride = gridDim.x * blockDim.x;
    int gid = blockIdx.x * blockDim.x + threadIdx.x;
    int ntasks = N * 16;
    for (int i = gid; i < ntasks; i += stride) {
        int n = i >> 4, s = i & 15;
        float4 v = ((const float4*)(nfeats + (size_t)n * DIN))[s];
        uint16_t h0, l0, h1, l1, h2, l2, h3, l3;
        bsplit(v.x, h0, l0); bsplit(v.y, h1, l1);
        bsplit(v.z, h2, l2); bsplit(v.w, h3, l3);
        uint2* row = (uint2*)(g_nsplit + (size_t)n * 128);
        row[s]      = make_uint2((uint32_t)h0 | ((uint32_t)h1 << 16),
                                 (uint32_t)h2 | ((uint32_t)h3 << 16));
        row[16 + s] = make_uint2((uint32_t)l0 | ((uint32_t)l1 << 16),
                                 (uint32_t)l2 | ((uint32_t)l3 << 16));
    }
    int etasks = E * 16;
    for (int i = gid; i < etasks; i += stride) {
        int e = i >> 4, s = i & 15;
        float4 v = ((const float4*)(efeats + (size_t)e * DIN))[s];
        uint16_t h0, l0, h1, l1, h2, l2, h3, l3;
        bsplit(v.x, h0, l0); bsplit(v.y, h1, l1);
        bsplit(v.z, h2, l2); bsplit(v.w, h3, l3);
        uint2* row = (uint2*)(g_esplit + (size_t)e * 128);
        row[s]      = make_uint2((uint32_t)h0 | ((uint32_t)h1 << 16),
                                 (uint32_t)h2 | ((uint32_t)h3 << 16));
        row[16 + s] = make_uint2((uint32_t)l0 | ((uint32_t)l1 << 16),
                                 (uint32_t)l2 | ((uint32_t)l3 << 16));
    }
}

// ---------------------------------------------------------------------------
// CSR build (runs on side stream, hidden under edge_kernel)
// ---------------------------------------------------------------------------
__global__ void hist_kernel(const int* __restrict__ dst, int E) {
    int stride = gridDim.x * blockDim.x;
    for (int e = blockIdx.x * blockDim.x + threadIdx.x; e < E; e += stride)
        atomicAdd(&g_cnt[dst[e]], 1);
}

__global__ void scan_kernel(int N) {
    __shared__ int part[1024];
    int tid = threadIdx.x;
    int per = (N + 1023) / 1024;
    int start = tid * per;
    int stop  = min(start + per, N);
    int sum = 0;
    for (int i = start; i < stop; i++) sum += g_cnt[i];
    part[tid] = sum;
    __syncthreads();
    for (int d = 1; d < 1024; d <<= 1) {
        int v = (tid >= d) ? part[tid - d] : 0;
        __syncthreads();
        part[tid] += v;
        __syncthreads();
    }
    int run = part[tid] - sum;
    for (int i = start; i < stop; i++) {
        g_off[i] = run;
        g_cur[i] = run;
        run += g_cnt[i];
    }
    if (tid == 1023) g_off[N] = run;
}

__global__ void bucket_kernel(const int* __restrict__ src,
                              const int* __restrict__ dst, int E) {
    int stride = gridDim.x * blockDim.x;
    for (int e = blockIdx.x * blockDim.x + threadIdx.x; e < E; e += stride) {
        int pos = atomicAdd(&g_cur[dst[e]], 1);
        g_eid[pos]  = e;
        g_esrc[pos] = src[e];
    }
}

// ---------------------------------------------------------------------------
// Edge kernel: R13/R15-proven version VERBATIM — persistent, W resident,
// per-tile self-contained cp.async pipeline (369.9 us / tensor 52.5%).
// ---------------------------------------------------------------------------
#define ASTRIDE 144
#define CHUNKB  36864
#define SW_OFF(c) ((uint32_t)((c) * CHUNKB))
#define SA_OFF(s) ((uint32_t)(110592 + (s) * CHUNKB))
#define LO_OFF  18432
#define SO_BS   184320
#define SO_WAS  184832
#define SO_TOTAL 184960

__global__ __launch_bounds__(512, 1)
void edge_kernel(const int* __restrict__ src,
                 const int* __restrict__ dst,
                 const float* __restrict__ b_edges,
                 const float* __restrict__ W_attn,
                 float* __restrict__ f_out,
                 int E, int ntiles) {
    extern __shared__ char smem[];
    float* bs  = (float*)(smem + SO_BS);
    float* was = (float*)(smem + SO_WAS);

    int tid  = threadIdx.x;
    int lane = tid & 31;
    int warp = tid >> 5;
    uint32_t sb = smem_u32(smem);
    int grid = gridDim.x;
    int t0 = blockIdx.x;
    if (t0 >= ntiles) return;     // before ANY cp.async

    if (tid < DOUT) bs[tid] = b_edges[tid];
    if (tid < 32)
        was[tid] = W_attn[tid * 4] + W_attn[tid * 4 + 1]
                 + W_attn[tid * 4 + 2] + W_attn[tid * 4 + 3];

    // ---- resident W: 3 chunks x 128 rows x 16 segs(16B); one group ----
#pragma unroll
    for (int it = 0; it < 12; it++) {
        int i   = tid + it * 512;          // 0..6143
        int c   = i >> 11;
        int n   = (i >> 4) & 127;
        int seg = i & 15;
        uint32_t dsto = SW_OFF(c) + ((seg < 8) ? 0 : LO_OFF) + n * ASTRIDE
                      + (seg & 7) * 16;
        const char* srcp = (const char*)g_Wps + ((size_t)c * 128 + n) * 256 + seg * 16;
        cp16(sb + dsto, srcp);
    }
    CP_COMMIT();   // W group; consumed by the first tile's wait(1)

    // ---- A-chunk issue: tile t, chunk c, stage s ----
    auto issue = [&](int t, int c, int s) {
        int e0 = t * TE;
#pragma unroll
        for (int it = 0; it < 4; it++) {
            int i   = tid + it * 512;      // 0..2047
            int le  = i >> 4;
            int seg = i & 15;
            int e   = e0 + le;
            int ee  = (e < E) ? e : (E - 1);
            const char* row;
            if (c == 0)      row = (const char*)(g_nsplit + (size_t)src[ee] * 128);
            else if (c == 1) row = (const char*)(g_esplit + (size_t)ee * 128);
            else             row = (const char*)(g_nsplit + (size_t)dst[ee] * 128);
            uint32_t dsto = SA_OFF(s) + ((seg < 8) ? 0 : LO_OFF) + le * ASTRIDE
                          + (seg & 7) * 16;
            cp16(sb + dsto, row + seg * 16);
        }
        CP_COMMIT();
    };

    // warp tile coords: 4m x 4n, 32x32 each; head = wn
    int wm = warp & 3;
    int wn = warp >> 2;
    int mrow0 = wm * 32;
    int nrow0 = wn * 32;
    uint32_t a_l_off = (uint32_t)((lane & 15) * ASTRIDE + (lane >> 4) * 16);
    uint32_t b_l_off = (uint32_t)(((lane & 7) + ((lane >> 4) << 3)) * ASTRIDE
                                + (((lane >> 3) & 1) << 4));
    int g   = lane >> 2;
    int tig = lane & 3;

    float acc[2][4][4];

    // compute one 64-K chunk: A from stage s, W from resident chunk c
    auto compute = [&](int c, int s) {
#pragma unroll
        for (int kk = 0; kk < 4; kk++) {
            uint32_t kb = kk * 32;
            uint32_t ah[2][4], al_[2][4], bh[2][4], bl_[2][4];
#pragma unroll
            for (int mt = 0; mt < 2; mt++) {
                uint32_t base = sb + SA_OFF(s)
                              + (mrow0 + mt * 16) * ASTRIDE + kb + a_l_off;
                ldsm_x4(ah[mt],  base);
                ldsm_x4(al_[mt], base + LO_OFF);
            }
#pragma unroll
            for (int p = 0; p < 2; p++) {
                uint32_t base = sb + SW_OFF(c)
                              + (nrow0 + p * 16) * ASTRIDE + kb + b_l_off;
                ldsm_x4(bh[p],  base);
                ldsm_x4(bl_[p], base + LO_OFF);
            }
#pragma unroll
            for (int mt = 0; mt < 2; mt++)
#pragma unroll
                for (int nt = 0; nt < 4; nt++) {
                    const uint32_t* bhf = &bh[nt >> 1][(nt & 1) * 2];
                    const uint32_t* blf = &bl_[nt >> 1][(nt & 1) * 2];
                    mma_bf16(acc[mt][nt], ah[mt], bhf);
                    mma_bf16(acc[mt][nt], ah[mt], blf);
                    mma_bf16(acc[mt][nt], al_[mt], bhf);
                }
        }
    };

    for (int t = t0; t < ntiles; t += grid) {
#pragma unroll
        for (int mt = 0; mt < 2; mt++)
#pragma unroll
            for (int nt = 0; nt < 4; nt++)
#pragma unroll
                for (int q = 0; q < 4; q++) acc[mt][nt][q] = 0.0f;

        issue(t, 0, 0);            // group: chunk0 -> stage0
        issue(t, 1, 1);            // group: chunk1 -> stage1

        CP_WAIT(1);                // chunk0 (and W on first tile) complete
        __syncthreads();
        compute(0, 0);
        __syncthreads();           // stage0 free
        issue(t, 2, 0);            // group: chunk2 -> stage0

        CP_WAIT(1);                // chunk1 complete
        __syncthreads();
        compute(1, 1);

        CP_WAIT(0);                // chunk2 complete (pipeline fully drained)
        __syncthreads();
        compute(2, 0);
        __syncthreads();           // all reads done before next tile's issues

        // ---- register epilogue: head h = wn ----
        int e0 = t * TE;
        int h  = wn;
#pragma unroll
        for (int mt = 0; mt < 2; mt++) {
#pragma unroll
            for (int rb = 0; rb < 2; rb++) {
                int e = e0 + mrow0 + mt * 16 + rb * 8 + g;
                float part = 0.0f;
#pragma unroll
                for (int nt = 0; nt < 4; nt++) {
                    int col  = nrow0 + nt * 8 + tig * 2;   // global column (bias)
                    int coli = nt * 8 + tig * 2;           // within-head (attn w)
                    float v0 = acc[mt][nt][rb * 2 + 0] + bs[col];
                    float v1 = acc[mt][nt][rb * 2 + 1] + bs[col + 1];
                    v0 = (v0 >= 0.f) ? v0 : 0.01f * v0;
                    v1 = (v1 >= 0.f) ? v1 : 0.01f * v1;
                    part += v0 * was[coli] + v1 * was[coli + 1];
                    if (e < E)
                        *(float2*)(f_out + (size_t)e * DOUT + col) =
                            make_float2(v0, v1);
                }
                part += __shfl_xor_sync(0xffffffffu, part, 1);
                part += __shfl_xor_sync(0xffffffffu, part, 2);
                if (tig == 0 && e < E) {
                    g_a[(size_t)e * 4 + h] = part;
                    atomicMaxFloat(&g_amax[(size_t)dst[e] * 4 + h], part);
                }
            }
        }
    }
}

// ---------------------------------------------------------------------------
// Fused softmax + aggregation: one warp per dst node. Single pass:
// h_out[n] = sum_e exp(a_e - amax)*ht[src_e] / sum_e exp(a_e - amax).
// Non-atomic output; writes every node (covers zero-init).
// ---------------------------------------------------------------------------
__global__ void aggregate_kernel(float* __restrict__ h_out, int N) {
    int n = (blockIdx.x * blockDim.x + threadIdx.x) >> 5;
    int lane = threadIdx.x & 31;
    if (n >= N) return;
    int beg = g_off[n];
    int end = g_off[n + 1];
    int h = lane >> 3;
    float amax = g_amax[(size_t)n * 4 + h];
    float den = 0.0f;
    float4 acc = make_float4(0.f, 0.f, 0.f, 0.f);
    for (int i = beg; i < end; i++) {
        int e = __ldg(&g_eid[i]);
        int s = __ldg(&g_esrc[i]);
        float ex = expf(g_a[(size_t)e * 4 + h] - amax);
        float4 ht = *reinterpret_cast<const float4*>(g_ht + (size_t)s * DOUT + lane * 4);
        den += ex;
        acc.x += ex * ht.x;
        acc.y += ex * ht.y;
        acc.z += ex * ht.z;
        acc.w += ex * ht.w;
    }
    float inv = (end > beg) ? 1.0f / den : 0.0f;
    *reinterpret_cast<float4*>(h_out + (size_t)n * DOUT + lane * 4) =
        make_float4(acc.x * inv, acc.y * inv, acc.z * inv, acc.w * inv);
}

// ---------------------------------------------------------------------------
extern "C" void kernel_launch(void* const* d_in, const int* in_sizes, int n_in,
                              void* d_out, int out_size) {
    const float* nfeats  = (const float*)d_in[0];
    const float* efeats  = (const float*)d_in[1];
    const int*   src     = (const int*)d_in[2];
    const int*   dst     = (const int*)d_in[3];
    const float* W_nodes = (const float*)d_in[4];
    const float* b_nodes = (const float*)d_in[5];
    const float* W_edges = (const float*)d_in[6];
    const float* b_edges = (const float*)d_in[7];
    const float* W_attn  = (const float*)d_in[8];

    int N = in_sizes[0] / DIN;
    int E = in_sizes[2];
    int ntiles = (E + TE - 1) / TE;

    float* h_out = (float*)d_out;
    float* f_out = (float*)d_out + (size_t)N * DOUT;

    cudaFuncSetAttribute(edge_kernel, cudaFuncAttributeMaxDynamicSharedMemorySize,
                         SO_TOTAL);

    // one-time host resources (created on correctness run; no device memory)
    static cudaStream_t s1 = nullptr, s2 = nullptr;
    static cudaEvent_t ev_fork = nullptr, ev_s1 = nullptr, ev_s2 = nullptr,
                       ev_csr = nullptr;
    if (s1 == nullptr) {
        cudaStreamCreateWithFlags(&s1, cudaStreamNonBlocking);
        cudaStreamCreateWithFlags(&s2, cudaStreamNonBlocking);
        cudaEventCreateWithFlags(&ev_fork, cudaEventDisableTiming);
        cudaEventCreateWithFlags(&ev_s1, cudaEventDisableTiming);
        cudaEventCreateWithFlags(&ev_s2, cudaEventDisableTiming);
        cudaEventCreateWithFlags(&ev_csr, cudaEventDisableTiming);
    }

    // fork: node (stream 0) || prep_w (s1) || prep_feats (s2)
    cudaEventRecord(ev_fork, 0);
    cudaStreamWaitEvent(s1, ev_fork, 0);
    cudaStreamWaitEvent(s2, ev_fork, 0);

    node_kernel<<<(N + 127) / 128, 512>>>(nfeats, W_nodes, b_nodes, N);
    prep_w_kernel<<<256, 256, 0, s1>>>(W_edges, N);
    prep_feats_kernel<<<1024, 256, 0, s2>>>(nfeats, efeats, N, E);

    cudaEventRecord(ev_s1, s1);
    cudaEventRecord(ev_s2, s2);
    cudaStreamWaitEvent(0, ev_s1, 0);
    cudaStreamWaitEvent(0, ev_s2, 0);

    // edge GEMM on main stream (launch #4 for ncu)
    edge_kernel<<<148, 512, SO_TOTAL>>>(src, dst, b_edges, W_attn, f_out, E, ntiles);

    // CSR build on s1, concurrent with edge_kernel (needs only src/dst and
    // g_cnt zeroed by prep_w, which is already ordered on s1)
    hist_kernel<<<512, 256, 0, s1>>>(dst, E);
    scan_kernel<<<1, 1024, 0, s1>>>(N);
    bucket_kernel<<<512, 256, 0, s1>>>(src, dst, E);
    cudaEventRecord(ev_csr, s1);

    // aggregation waits on edge (stream order) + CSR (event)
    cudaStreamWaitEvent(0, ev_csr, 0);
    aggregate_kernel<<<(N * 32 + 255) / 256, 256>>>(h_out, N);
}

// round 17
// speedup vs baseline: 1.2714x; 1.0714x over previous
#include <cuda_runtime.h>
#include <cuda_bf16.h>
#include <math.h>
#include <stdint.h>

#define MAXN 50000
#define MAXE 800000
#define DIN 64
#define DOUT 128
#define KDIM 192
#define TE 128                 // edges per tile (persistent kernel)

// Scratch (device globals)
__device__ float g_ht[MAXN * DOUT];
__device__ float g_a[MAXE * 4];          // attention logits
__device__ float g_amax[MAXN * 4];
// CSR scratch
__device__ int   g_cnt[MAXN];
__device__ int   g_off[MAXN + 1];
__device__ int   g_cur[MAXN];
__device__ int   g_eid[MAXE];
__device__ int   g_esrc[MAXE];
// pre-split node feats: row = [64 bf16 hi | 64 bf16 lo] = 256B
__device__ __nv_bfloat16 g_nsplit[MAXN * 128];
__device__ __nv_bfloat16 g_Wps[3 * 128 * 128];   // [chunk][n][hi64|lo64]

__device__ __forceinline__ void atomicMaxFloat(float* addr, float value) {
    if (value >= 0.0f) atomicMax((int*)addr, __float_as_int(value));
    else               atomicMin((unsigned int*)addr, __float_as_uint(value));
}

__device__ __forceinline__ void mma_bf16(float* d, const uint32_t* a, const uint32_t* b) {
    asm volatile(
        "mma.sync.aligned.m16n8k16.row.col.f32.bf16.bf16.f32 "
        "{%0,%1,%2,%3}, {%4,%5,%6,%7}, {%8,%9}, {%0,%1,%2,%3};"
        : "+f"(d[0]), "+f"(d[1]), "+f"(d[2]), "+f"(d[3])
        : "r"(a[0]), "r"(a[1]), "r"(a[2]), "r"(a[3]), "r"(b[0]), "r"(b[1]));
}
__device__ __forceinline__ void ldsm_x4(uint32_t* r, uint32_t addr) {
    asm volatile("ldmatrix.sync.aligned.m8n8.x4.shared.b16 {%0,%1,%2,%3}, [%4];"
        : "=r"(r[0]), "=r"(r[1]), "=r"(r[2]), "=r"(r[3]) : "r"(addr));
}
__device__ __forceinline__ uint32_t smem_u32(const void* p) {
    uint32_t a;
    asm("{ .reg .u64 t; cvta.to.shared.u64 t, %1; cvt.u32.u64 %0, t; }"
        : "=r"(a) : "l"(p));
    return a;
}
__device__ __forceinline__ void cp16(uint32_t smem_dst, const void* gsrc) {
    asm volatile("cp.async.cg.shared.global [%0], [%1], 16;"
        :: "r"(smem_dst), "l"(gsrc));
}
#define CP_COMMIT() asm volatile("cp.async.commit_group;" ::: "memory")
#define CP_WAIT(n)  asm volatile("cp.async.wait_group %0;" :: "n"(n) : "memory")

__device__ __forceinline__ void bsplit(float x, uint16_t& h, uint16_t& l) {
    __nv_bfloat16 bh = __float2bfloat16_rn(x);
    float r = x - __bfloat162float(bh);
    __nv_bfloat16 bl = __float2bfloat16_rn(r);
    h = __bfloat16_as_ushort(bh);
    l = __bfloat16_as_ushort(bl);
}

__device__ __forceinline__ unsigned long long pack2(float lo, float hi) {
    unsigned long long r;
    asm("mov.b64 %0, {%1, %2};" : "=l"(r) : "f"(lo), "f"(hi));
    return r;
}
__device__ __forceinline__ void unpack2(unsigned long long v, float& lo, float& hi) {
    asm("mov.b64 {%0, %1}, %2;" : "=f"(lo), "=f"(hi) : "l"(v));
}
__device__ __forceinline__ void fma2(unsigned long long& d, unsigned long long a,
                                     unsigned long long b) {
    asm("fma.rn.f32x2 %0, %1, %2, %0;" : "+l"(d) : "l"(a), "l"(b));
}

// ---------------------------------------------------------------------------
// node transform: tiled f32x2 GEMM, 128 nodes x 128 cols per block
// ---------------------------------------------------------------------------
__global__ __launch_bounds__(512, 1)
void node_kernel(const float* __restrict__ nfeats,
                 const float* __restrict__ W_nodes,
                 const float* __restrict__ b_nodes,
                 int N) {
    __shared__ float Ws[DIN * DOUT];    // 32 KB
    __shared__ float Xt[DIN * 128];     // 32 KB, transposed [k][node]
    __shared__ float bsh[DOUT];

    int tid  = threadIdx.x;
    int lane = tid & 31;
    int warp = tid >> 5;
    int n0   = blockIdx.x * 128;

    for (int i = tid; i < DIN * DOUT / 4; i += 512)
        ((float4*)Ws)[i] = ((const float4*)W_nodes)[i];
    if (tid < DOUT) bsh[tid] = b_nodes[tid];

#pragma unroll
    for (int it = 0; it < 4; it++) {
        int i   = tid + it * 512;
        int ln  = i >> 4;
        int seg = i & 15;
        int n   = n0 + ln;
        float4 v = make_float4(0.f, 0.f, 0.f, 0.f);
        if (n < N) v = ((const float4*)(nfeats + (size_t)n * DIN))[seg];
        int k0 = seg * 4;
        Xt[(k0 + 0) * 128 + ln] = v.x;
        Xt[(k0 + 1) * 128 + ln] = v.y;
        Xt[(k0 + 2) * 128 + ln] = v.z;
        Xt[(k0 + 3) * 128 + ln] = v.w;
    }
    __syncthreads();

    int c0  = lane * 4;
    int ln0 = warp * 8;

    unsigned long long acc[4][4];
#pragma unroll
    for (int p = 0; p < 4; p++)
#pragma unroll
        for (int c = 0; c < 4; c++)
            acc[p][c] = pack2(bsh[c0 + c], bsh[c0 + c]);

#pragma unroll 2
    for (int k = 0; k < DIN; k++) {
        float4 w = *reinterpret_cast<const float4*>(Ws + k * DOUT + c0);
        unsigned long long wd[4];
        wd[0] = pack2(w.x, w.x);
        wd[1] = pack2(w.y, w.y);
        wd[2] = pack2(w.z, w.z);
        wd[3] = pack2(w.w, w.w);
        ulonglong2 sA = *reinterpret_cast<const ulonglong2*>(Xt + k * 128 + ln0);
        ulonglong2 sB = *reinterpret_cast<const ulonglong2*>(Xt + k * 128 + ln0 + 4);
        unsigned long long sp[4] = {sA.x, sA.y, sB.x, sB.y};
#pragma unroll
        for (int p = 0; p < 4; p++)
#pragma unroll
            for (int c = 0; c < 4; c++)
                fma2(acc[p][c], sp[p], wd[c]);
    }

#pragma unroll
    for (int p = 0; p < 4; p++) {
        float lo[4], hi[4];
#pragma unroll
        for (int c = 0; c < 4; c++) unpack2(acc[p][c], lo[c], hi[c]);
        int nA = n0 + ln0 + 2 * p;
        if (nA < N)
            *(float4*)(g_ht + (size_t)nA * DOUT + c0) =
                make_float4(lo[0], lo[1], lo[2], lo[3]);
        if (nA + 1 < N)
            *(float4*)(g_ht + (size_t)(nA + 1) * DOUT + c0) =
                make_float4(hi[0], hi[1], hi[2], hi[3]);
    }
}

// ---------------------------------------------------------------------------
// prep_w: W split (chunk-major) + nfeats split + init amax + zero CSR counters
// ---------------------------------------------------------------------------
__global__ void prep_w_kernel(const float* __restrict__ W_edges,
                              const float* __restrict__ nfeats, int N) {
    int stride = gridDim.x * blockDim.x;
    int gid = blockIdx.x * blockDim.x + threadIdx.x;
    for (int i = gid; i < 3 * 128 * 64; i += stride) {
        int c  = i / (128 * 64);
        int n  = (i / 64) & 127;
        int kk = i & 63;
        float x = W_edges[(size_t)(64 * c + kk) * DOUT + n];
        uint16_t h, l;
        bsplit(x, h, l);
        __nv_bfloat16* row = g_Wps + ((size_t)c * 128 + n) * 128;
        row[kk]      = __ushort_as_bfloat16(h);
        row[64 + kk] = __ushort_as_bfloat16(l);
    }
    int ntasks = N * 16;
    for (int i = gid; i < ntasks; i += stride) {
        int n = i >> 4, s = i & 15;
        float4 v = ((const float4*)(nfeats + (size_t)n * DIN))[s];
        uint16_t h0, l0, h1, l1, h2, l2, h3, l3;
        bsplit(v.x, h0, l0); bsplit(v.y, h1, l1);
        bsplit(v.z, h2, l2); bsplit(v.w, h3, l3);
        uint2* row = (uint2*)(g_nsplit + (size_t)n * 128);
        row[s]      = make_uint2((uint32_t)h0 | ((uint32_t)h1 << 16),
                                 (uint32_t)h2 | ((uint32_t)h3 << 16));
        row[16 + s] = make_uint2((uint32_t)l0 | ((uint32_t)l1 << 16),
                                 (uint32_t)l2 | ((uint32_t)l3 << 16));
    }
    for (int i = gid; i < N * 4; i += stride)
        g_amax[i] = -INFINITY;
    for (int i = gid; i < N; i += stride)
        g_cnt[i] = 0;
}

// ---------------------------------------------------------------------------
// CSR build (side stream, concurrent with edge_kernel)
// ---------------------------------------------------------------------------
__global__ void hist_kernel(const int* __restrict__ dst, int E) {
    int stride = gridDim.x * blockDim.x;
    for (int e = blockIdx.x * blockDim.x + threadIdx.x; e < E; e += stride)
        atomicAdd(&g_cnt[dst[e]], 1);
}

__global__ void scan_kernel(int N) {
    __shared__ int part[1024];
    int tid = threadIdx.x;
    int per = (N + 1023) / 1024;
    int start = tid * per;
    int stop  = min(start + per, N);
    int sum = 0;
    for (int i = start; i < stop; i++) sum += g_cnt[i];
    part[tid] = sum;
    __syncthreads();
    for (int d = 1; d < 1024; d <<= 1) {
        int v = (tid >= d) ? part[tid - d] : 0;
        __syncthreads();
        part[tid] += v;
        __syncthreads();
    }
    int run = part[tid] - sum;
    for (int i = start; i < stop; i++) {
        g_off[i] = run;
        g_cur[i] = run;
        run += g_cnt[i];
    }
    if (tid == 1023) g_off[N] = run;
}

__global__ void bucket_kernel(const int* __restrict__ src,
                              const int* __restrict__ dst, int E) {
    int stride = gridDim.x * blockDim.x;
    for (int e = blockIdx.x * blockDim.x + threadIdx.x; e < E; e += stride) {
        int pos = atomicAdd(&g_cur[dst[e]], 1);
        g_eid[pos]  = e;
        g_esrc[pos] = src[e];
    }
}

// ---------------------------------------------------------------------------
// Edge kernel: persistent, W resident, per-tile cp.async pipeline (R13-proven
// structure). NEW: chunk1 stages raw fp32 efeats and converts in-kernel —
// eliminates the global esplit pass (no traffic increase: 256B/edge both ways)
// ---------------------------------------------------------------------------
#define ASTRIDE 144
#define CHUNKB  36864
#define SW_OFF(c) ((uint32_t)((c) * CHUNKB))
#define SA_OFF(s) ((uint32_t)(110592 + (s) * CHUNKB))
#define LO_OFF  18432
#define SO_BS   184320
#define SO_WAS  184832
#define SO_EF32 184960                  // raw fp32 efeats staging: 128*256 B
#define SO_TOTAL 217728

__global__ __launch_bounds__(512, 1)
void edge_kernel(const int* __restrict__ src,
                 const int* __restrict__ dst,
                 const float* __restrict__ efeats,
                 const float* __restrict__ b_edges,
                 const float* __restrict__ W_attn,
                 float* __restrict__ f_out,
                 int E, int ntiles) {
    extern __shared__ char smem[];
    float* bs  = (float*)(smem + SO_BS);
    float* was = (float*)(smem + SO_WAS);

    int tid  = threadIdx.x;
    int lane = tid & 31;
    int warp = tid >> 5;
    uint32_t sb = smem_u32(smem);
    int grid = gridDim.x;
    int t0 = blockIdx.x;
    if (t0 >= ntiles) return;     // before ANY cp.async

    if (tid < DOUT) bs[tid] = b_edges[tid];
    if (tid < 32)
        was[tid] = W_attn[tid * 4] + W_attn[tid * 4 + 1]
                 + W_attn[tid * 4 + 2] + W_attn[tid * 4 + 3];

    // ---- resident W: 3 chunks x 128 rows x 16 segs(16B); one group ----
#pragma unroll
    for (int it = 0; it < 12; it++) {
        int i   = tid + it * 512;          // 0..6143
        int c   = i >> 11;
        int n   = (i >> 4) & 127;
        int seg = i & 15;
        uint32_t dsto = SW_OFF(c) + ((seg < 8) ? 0 : LO_OFF) + n * ASTRIDE
                      + (seg & 7) * 16;
        const char* srcp = (const char*)g_Wps + ((size_t)c * 128 + n) * 256 + seg * 16;
        cp16(sb + dsto, srcp);
    }
    CP_COMMIT();   // W group; consumed by the first tile's wait(1)

    // ---- A-chunk issue: tile t, chunk c, stage s (chunk1 -> fp32 staging) --
    auto issue = [&](int t, int c, int s) {
#pragma unroll
        for (int it = 0; it < 4; it++) {
            int i   = tid + it * 512;      // 0..2047
            int le  = i >> 4;
            int seg = i & 15;
            int e   = t * TE + le;
            int ee  = (e < E) ? e : (E - 1);
            if (c == 1) {
                // raw fp32 row -> linear staging [le][256B]
                cp16(sb + SO_EF32 + le * 256 + seg * 16,
                     (const char*)(efeats + (size_t)ee * DIN) + seg * 16);
            } else {
                const char* row = (c == 0)
                    ? (const char*)(g_nsplit + (size_t)src[ee] * 128)
                    : (const char*)(g_nsplit + (size_t)dst[ee] * 128);
                uint32_t dsto = SA_OFF(s) + ((seg < 8) ? 0 : LO_OFF)
                              + le * ASTRIDE + (seg & 7) * 16;
                cp16(sb + dsto, row + seg * 16);
            }
        }
        CP_COMMIT();
    };

    // warp tile coords: 4m x 4n, 32x32 each; head = wn
    int wm = warp & 3;
    int wn = warp >> 2;
    int mrow0 = wm * 32;
    int nrow0 = wn * 32;
    uint32_t a_l_off = (uint32_t)((lane & 15) * ASTRIDE + (lane >> 4) * 16);
    uint32_t b_l_off = (uint32_t)(((lane & 7) + ((lane >> 4) << 3)) * ASTRIDE
                                + (((lane >> 3) & 1) << 4));
    int g   = lane >> 2;
    int tig = lane & 3;

    float acc[2][4][4];

    // compute one 64-K chunk: A from stage s, W from resident chunk c
    auto compute = [&](int c, int s) {
#pragma unroll
        for (int kk = 0; kk < 4; kk++) {
            uint32_t kb = kk * 32;
            uint32_t ah[2][4], al_[2][4], bh[2][4], bl_[2][4];
#pragma unroll
            for (int mt = 0; mt < 2; mt++) {
                uint32_t base = sb + SA_OFF(s)
                              + (mrow0 + mt * 16) * ASTRIDE + kb + a_l_off;
                ldsm_x4(ah[mt],  base);
                ldsm_x4(al_[mt], base + LO_OFF);
            }
#pragma unroll
            for (int p = 0; p < 2; p++) {
                uint32_t base = sb + SW_OFF(c)
                              + (nrow0 + p * 16) * ASTRIDE + kb + b_l_off;
                ldsm_x4(bh[p],  base);
                ldsm_x4(bl_[p], base + LO_OFF);
            }
#pragma unroll
            for (int mt = 0; mt < 2; mt++)
#pragma unroll
                for (int nt = 0; nt < 4; nt++) {
                    const uint32_t* bhf = &bh[nt >> 1][(nt & 1) * 2];
                    const uint32_t* blf = &bl_[nt >> 1][(nt & 1) * 2];
                    mma_bf16(acc[mt][nt], ah[mt], bhf);
                    mma_bf16(acc[mt][nt], ah[mt], blf);
                    mma_bf16(acc[mt][nt], al_[mt], bhf);
                }
        }
    };

    for (int t = t0; t < ntiles; t += grid) {
#pragma unroll
        for (int mt = 0; mt < 2; mt++)
#pragma unroll
            for (int nt = 0; nt < 4; nt++)
#pragma unroll
                for (int q = 0; q < 4; q++) acc[mt][nt][q] = 0.0f;

        issue(t, 0, 0);            // group: chunk0 -> stage0
        issue(t, 1, 1);            // group: chunk1 (fp32) -> EF32 staging

        CP_WAIT(1);                // chunk0 (and W on first tile) complete
        __syncthreads();
        compute(0, 0);
        __syncthreads();           // stage0 free
        issue(t, 2, 0);            // group: chunk2 -> stage0

        CP_WAIT(1);                // chunk1 fp32 staged
        __syncthreads();           // staging visible to all threads
        // ---- in-kernel bf16 split: EF32 staging -> stage1 hi/lo ----
#pragma unroll
        for (int it = 0; it < 4; it++) {
            int i   = tid + it * 512;
            int le  = i >> 4;
            int seg = i & 15;
            float4 v = *(const float4*)(smem + SO_EF32 + le * 256 + seg * 16);
            uint16_t h0, l0, h1, l1, h2, l2, h3, l3;
            bsplit(v.x, h0, l0); bsplit(v.y, h1, l1);
            bsplit(v.z, h2, l2); bsplit(v.w, h3, l3);
            uint2 hv = make_uint2((uint32_t)h0 | ((uint32_t)h1 << 16),
                                  (uint32_t)h2 | ((uint32_t)h3 << 16));
            uint2 lv = make_uint2((uint32_t)l0 | ((uint32_t)l1 << 16),
                                  (uint32_t)l2 | ((uint32_t)l3 << 16));
            *(uint2*)(smem + SA_OFF(1) + le * ASTRIDE + seg * 8) = hv;
            *(uint2*)(smem + SA_OFF(1) + LO_OFF + le * ASTRIDE + seg * 8) = lv;
        }
        __syncthreads();           // stage1 ready
        compute(1, 1);

        CP_WAIT(0);                // chunk2 complete (pipeline fully drained)
        __syncthreads();
        compute(2, 0);
        __syncthreads();           // all reads done before next tile's issues

        // ---- register epilogue: head h = wn ----
        int e0 = t * TE;
        int h  = wn;
#pragma unroll
        for (int mt = 0; mt < 2; mt++) {
#pragma unroll
            for (int rb = 0; rb < 2; rb++) {
                int e = e0 + mrow0 + mt * 16 + rb * 8 + g;
                float part = 0.0f;
#pragma unroll
                for (int nt = 0; nt < 4; nt++) {
                    int col  = nrow0 + nt * 8 + tig * 2;   // global column (bias)
                    int coli = nt * 8 + tig * 2;           // within-head (attn w)
                    float v0 = acc[mt][nt][rb * 2 + 0] + bs[col];
                    float v1 = acc[mt][nt][rb * 2 + 1] + bs[col + 1];
                    v0 = (v0 >= 0.f) ? v0 : 0.01f * v0;
                    v1 = (v1 >= 0.f) ? v1 : 0.01f * v1;
                    part += v0 * was[coli] + v1 * was[coli + 1];
                    if (e < E)
                        *(float2*)(f_out + (size_t)e * DOUT + col) =
                            make_float2(v0, v1);
                }
                part += __shfl_xor_sync(0xffffffffu, part, 1);
                part += __shfl_xor_sync(0xffffffffu, part, 2);
                if (tig == 0 && e < E) {
                    g_a[(size_t)e * 4 + h] = part;
                    atomicMaxFloat(&g_amax[(size_t)dst[e] * 4 + h], part);
                }
            }
        }
    }
}

// ---------------------------------------------------------------------------
// Fused softmax + aggregation: one warp per dst node (R16-proven).
// ---------------------------------------------------------------------------
__global__ void aggregate_kernel(float* __restrict__ h_out, int N) {
    int n = (blockIdx.x * blockDim.x + threadIdx.x) >> 5;
    int lane = threadIdx.x & 31;
    if (n >= N) return;
    int beg = g_off[n];
    int end = g_off[n + 1];
    int h = lane >> 3;
    float amax = g_amax[(size_t)n * 4 + h];
    float den = 0.0f;
    float4 acc = make_float4(0.f, 0.f, 0.f, 0.f);
    for (int i = beg; i < end; i++) {
        int e = __ldg(&g_eid[i]);
        int s = __ldg(&g_esrc[i]);
        float ex = expf(g_a[(size_t)e * 4 + h] - amax);
        float4 ht = *reinterpret_cast<const float4*>(g_ht + (size_t)s * DOUT + lane * 4);
        den += ex;
        acc.x += ex * ht.x;
        acc.y += ex * ht.y;
        acc.z += ex * ht.z;
        acc.w += ex * ht.w;
    }
    float inv = (end > beg) ? 1.0f / den : 0.0f;
    *reinterpret_cast<float4*>(h_out + (size_t)n * DOUT + lane * 4) =
        make_float4(acc.x * inv, acc.y * inv, acc.z * inv, acc.w * inv);
}

// ---------------------------------------------------------------------------
extern "C" void kernel_launch(void* const* d_in, const int* in_sizes, int n_in,
                              void* d_out, int out_size) {
    const float* nfeats  = (const float*)d_in[0];
    const float* efeats  = (const float*)d_in[1];
    const int*   src     = (const int*)d_in[2];
    const int*   dst     = (const int*)d_in[3];
    const float* W_nodes = (const float*)d_in[4];
    const float* b_nodes = (const float*)d_in[5];
    const float* W_edges = (const float*)d_in[6];
    const float* b_edges = (const float*)d_in[7];
    const float* W_attn  = (const float*)d_in[8];

    int N = in_sizes[0] / DIN;
    int E = in_sizes[2];
    int ntiles = (E + TE - 1) / TE;

    float* h_out = (float*)d_out;
    float* f_out = (float*)d_out + (size_t)N * DOUT;

    cudaFuncSetAttribute(edge_kernel, cudaFuncAttributeMaxDynamicSharedMemorySize,
                         SO_TOTAL);

    // one-time host resources (created on correctness run; no device memory)
    static cudaStream_t s1 = nullptr;
    static cudaEvent_t ev_fork = nullptr, ev_s1 = nullptr, ev_csr = nullptr;
    if (s1 == nullptr) {
        cudaStreamCreateWithFlags(&s1, cudaStreamNonBlocking);
        cudaEventCreateWithFlags(&ev_fork, cudaEventDisableTiming);
        cudaEventCreateWithFlags(&ev_s1, cudaEventDisableTiming);
        cudaEventCreateWithFlags(&ev_csr, cudaEventDisableTiming);
    }

    // fork: node (stream 0) || prep_w + hist (s1)
    cudaEventRecord(ev_fork, 0);
    cudaStreamWaitEvent(s1, ev_fork, 0);

    node_kernel<<<(N + 127) / 128, 512>>>(nfeats, W_nodes, b_nodes, N);   // launch 1
    prep_w_kernel<<<512, 256, 0, s1>>>(W_edges, nfeats, N);               // launch 2
    hist_kernel<<<512, 256, 0, s1>>>(dst, E);                             // launch 3

    cudaEventRecord(ev_s1, s1);      // edge needs g_Wps + g_nsplit from prep_w
    cudaStreamWaitEvent(0, ev_s1, 0);

    // edge GEMM on main stream (launch #4 for ncu)
    edge_kernel<<<148, 512, SO_TOTAL>>>(src, dst, efeats, b_edges, W_attn,
                                        f_out, E, ntiles);

    // rest of CSR build on s1, concurrent with edge_kernel
    scan_kernel<<<1, 1024, 0, s1>>>(N);
    bucket_kernel<<<512, 256, 0, s1>>>(src, dst, E);
    cudaEventRecord(ev_csr, s1);

    // aggregation waits on edge (stream order) + CSR (event)
    cudaStreamWaitEvent(0, ev_csr, 0);
    aggregate_kernel<<<(N * 32 + 255) / 256, 256>>>(h_out, N);
}